// round 5
// baseline (speedup 1.0000x reference)
#include <cuda_runtime.h>
#include <cuda_bf16.h>
#include <math.h>

// Problem constants
#define Bz 4
#define Sz 2048
#define Dz 2048
#define NHz 16
#define DHz 128

#define TOT (4UL*2048UL*2048UL)   // B*S*D elements

// Scratch (allocation-free rule: __device__ globals)
__device__ float g_Q[TOT];
__device__ float g_K[TOT];
__device__ float g_V[TOT];
__device__ float g_A[TOT];
__device__ float g_R[TOT];

// ---------------------------------------------------------------------------
// GEMM: C[M,N] = A[M,K] @ B[K,N] (+ Res).  128x128 tile, 8x8 per thread.
// ---------------------------------------------------------------------------
__global__ __launch_bounds__(256) void gemm128(
    const float* __restrict__ A, const float* __restrict__ B,
    const float* __restrict__ Res, float* __restrict__ C,
    int M, int N, int K)
{
    __shared__ float sA[128][16];
    __shared__ float sB[16][136];   // padded stride 136 (16B-aligned rows)

    const int tid = threadIdx.x;
    const int tx = tid & 15, ty = tid >> 4;
    const int m0 = blockIdx.y * 128, n0 = blockIdx.x * 128;

    float acc[8][8];
#pragma unroll
    for (int i = 0; i < 8; i++)
#pragma unroll
        for (int j = 0; j < 8; j++) acc[i][j] = 0.f;

    for (int k0 = 0; k0 < K; k0 += 16) {
#pragma unroll
        for (int r = 0; r < 8; r++) {
            int e = r * 256 + tid;
            int row = e >> 4, col = e & 15;
            sA[row][col] = A[(long)(m0 + row) * K + k0 + col];
        }
#pragma unroll
        for (int r = 0; r < 8; r++) {
            int e = r * 256 + tid;
            int row = e >> 7, col = e & 127;
            sB[row][col] = B[(long)(k0 + row) * N + n0 + col];
        }
        __syncthreads();
#pragma unroll
        for (int kk = 0; kk < 16; kk++) {
            float a[8], b[8];
#pragma unroll
            for (int i = 0; i < 8; i++) a[i] = sA[ty * 8 + i][kk];
            float4 b0 = *(const float4*)&sB[kk][tx * 8];
            float4 b1 = *(const float4*)&sB[kk][tx * 8 + 4];
            b[0]=b0.x; b[1]=b0.y; b[2]=b0.z; b[3]=b0.w;
            b[4]=b1.x; b[5]=b1.y; b[6]=b1.z; b[7]=b1.w;
#pragma unroll
            for (int i = 0; i < 8; i++)
#pragma unroll
                for (int j = 0; j < 8; j++) acc[i][j] += a[i] * b[j];
        }
        __syncthreads();
    }

#pragma unroll
    for (int i = 0; i < 8; i++) {
        long row = m0 + ty * 8 + i;
        long base = row * N + n0 + tx * 8;
#pragma unroll
        for (int j = 0; j < 8; j++) {
            float v = acc[i][j];
            if (Res) v += Res[base + j];
            C[base + j] = v;
        }
    }
}

// ---------------------------------------------------------------------------
// RoPE: in-place on (B,S,NH*128) with interleaved pairs per head
// ---------------------------------------------------------------------------
__global__ void rope_kernel(float* __restrict__ X,
                            const float* __restrict__ cosb,
                            const float* __restrict__ sinb)
{
    int idx = blockIdx.x * blockDim.x + threadIdx.x;  // B*S*NH*64 threads
    int i = idx & 63;
    int h = (idx >> 6) & 15;
    int s = (idx >> 10) & 2047;
    int b = idx >> 21;
    long base = ((long)(b * Sz + s)) * Dz + h * DHz + 2 * i;
    float c = cosb[s * 64 + i], sn = sinb[s * 64 + i];
    float x1 = X[base], x2 = X[base + 1];
    X[base]     = x1 * c - x2 * sn;
    X[base + 1] = x1 * sn + x2 * c;
}

// ---------------------------------------------------------------------------
// Flash attention: 1 CTA = (b, h, 64-row q-tile); online softmax over 64-key tiles
// mask is int32 (reference bool -> harness int32): nonzero means MASKED (-inf).
// ---------------------------------------------------------------------------
#define FL_SMEM ((64*128 + 64*129 + 64*128 + 64*64) * 4)

__global__ __launch_bounds__(256) void flash_kernel(
    const float* __restrict__ Q, const float* __restrict__ K,
    const float* __restrict__ V, const int* __restrict__ mask,
    float* __restrict__ O)
{
    extern __shared__ float sm[];
    float* sQ = sm;                 // 64 x 128
    float* sK = sQ + 64 * 128;      // 64 x 129 (padded)
    float* sV = sK + 64 * 129;      // 64 x 128
    float* sS = sV + 64 * 128;      // 64 x 64

    const int tid = threadIdx.x;
    const int tx = tid & 15, ty = tid >> 4;
    const int blk = blockIdx.x;
    const int qt = blk & 31;
    const int h  = (blk >> 5) & 15;
    const int b  = blk >> 9;
    const int q0 = qt * 64;
    const float scale = 0.08838834764831845f;   // 1/sqrt(128)

    // load Q tile
#pragma unroll
    for (int r = 0; r < 32; r++) {
        int e = r * 256 + tid;
        int row = e >> 7, col = e & 127;
        sQ[row * 128 + col] = Q[((long)(b * Sz + q0 + row)) * Dz + h * DHz + col];
    }

    float m_i[4], l_i[4], o[4][8];
#pragma unroll
    for (int i = 0; i < 4; i++) {
        m_i[i] = -1e30f; l_i[i] = 0.f;
#pragma unroll
        for (int c = 0; c < 8; c++) o[i][c] = 0.f;
    }

    const int* mrow = mask + (long)b * Sz;

    for (int k0 = 0; k0 < Sz; k0 += 64) {
        __syncthreads();   // protect sK/sV/sS from previous iteration
#pragma unroll
        for (int r = 0; r < 32; r++) {
            int e = r * 256 + tid;
            int row = e >> 7, col = e & 127;
            long g = ((long)(b * Sz + k0 + row)) * Dz + h * DHz + col;
            sK[row * 129 + col] = K[g];
            sV[row * 128 + col] = V[g];
        }
        __syncthreads();

        // scores 4x4 per thread
        float accs[4][4];
#pragma unroll
        for (int i = 0; i < 4; i++)
#pragma unroll
            for (int j = 0; j < 4; j++) accs[i][j] = 0.f;

#pragma unroll 4
        for (int k = 0; k < 128; k++) {
            float a[4], bb[4];
#pragma unroll
            for (int i = 0; i < 4; i++) a[i]  = sQ[(ty * 4 + i) * 128 + k];
#pragma unroll
            for (int j = 0; j < 4; j++) bb[j] = sK[(tx * 4 + j) * 129 + k];
#pragma unroll
            for (int i = 0; i < 4; i++)
#pragma unroll
                for (int j = 0; j < 4; j++) accs[i][j] += a[i] * bb[j];
        }

        // mask + scale  (int32 mask: nonzero == masked)
        float sv[4][4];
#pragma unroll
        for (int j = 0; j < 4; j++) {
            bool msk = mrow[k0 + tx * 4 + j] != 0;
#pragma unroll
            for (int i = 0; i < 4; i++)
                sv[i][j] = msk ? -1e30f : accs[i][j] * scale;
        }

        // online softmax per row; rows for a given ty live in one half-warp (16 lanes)
#pragma unroll
        for (int i = 0; i < 4; i++) {
            float tm = fmaxf(fmaxf(sv[i][0], sv[i][1]), fmaxf(sv[i][2], sv[i][3]));
#pragma unroll
            for (int d = 1; d < 16; d <<= 1)
                tm = fmaxf(tm, __shfl_xor_sync(0xffffffffu, tm, d));
            float nm = fmaxf(m_i[i], tm);
            float corr = __expf(m_i[i] - nm);
            float p[4], ps = 0.f;
#pragma unroll
            for (int j = 0; j < 4; j++) { p[j] = __expf(sv[i][j] - nm); ps += p[j]; }
#pragma unroll
            for (int d = 1; d < 16; d <<= 1)
                ps += __shfl_xor_sync(0xffffffffu, ps, d);
            l_i[i] = l_i[i] * corr + ps;
            m_i[i] = nm;
#pragma unroll
            for (int c = 0; c < 8; c++) o[i][c] *= corr;
#pragma unroll
            for (int j = 0; j < 4; j++)
                sS[(ty * 4 + i) * 64 + tx * 4 + j] = p[j];
        }
        __syncthreads();

        // O += P @ V   (thread covers rows ty*4.., cols tx*8..)
#pragma unroll 4
        for (int kc = 0; kc < 64; kc++) {
            float4 v0 = *(const float4*)&sV[kc * 128 + tx * 8];
            float4 v1 = *(const float4*)&sV[kc * 128 + tx * 8 + 4];
#pragma unroll
            for (int i = 0; i < 4; i++) {
                float s = sS[(ty * 4 + i) * 64 + kc];
                o[i][0] += s * v0.x; o[i][1] += s * v0.y;
                o[i][2] += s * v0.z; o[i][3] += s * v0.w;
                o[i][4] += s * v1.x; o[i][5] += s * v1.y;
                o[i][6] += s * v1.z; o[i][7] += s * v1.w;
            }
        }
    }

    // epilogue: normalize and store
#pragma unroll
    for (int i = 0; i < 4; i++) {
        float inv = 1.f / l_i[i];
        long base = ((long)(b * Sz + q0 + ty * 4 + i)) * Dz + h * DHz + tx * 8;
        float4 r0 = { o[i][0]*inv, o[i][1]*inv, o[i][2]*inv, o[i][3]*inv };
        float4 r1 = { o[i][4]*inv, o[i][5]*inv, o[i][6]*inv, o[i][7]*inv };
        *(float4*)&O[base]     = r0;
        *(float4*)&O[base + 4] = r1;
    }
}

// ---------------------------------------------------------------------------
// LayerNorm over last dim (2048), one CTA per row
// ---------------------------------------------------------------------------
__global__ __launch_bounds__(256) void ln_kernel(
    const float* __restrict__ X, const float* __restrict__ gamma,
    const float* __restrict__ beta, float* __restrict__ Y)
{
    const int row = blockIdx.x;
    const int tid = threadIdx.x;
    const float* x = X + (long)row * Dz;

    float v[8], s = 0.f, s2 = 0.f;
#pragma unroll
    for (int r = 0; r < 8; r++) {
        float t = x[r * 256 + tid];
        v[r] = t; s += t; s2 += t * t;
    }
#pragma unroll
    for (int d = 16; d >= 1; d >>= 1) {
        s  += __shfl_xor_sync(0xffffffffu, s,  d);
        s2 += __shfl_xor_sync(0xffffffffu, s2, d);
    }
    __shared__ float rs[8], rs2[8];
    __shared__ float s_mean, s_rstd;
    int wid = tid >> 5, lane = tid & 31;
    if (lane == 0) { rs[wid] = s; rs2[wid] = s2; }
    __syncthreads();
    if (tid == 0) {
        float S = 0.f, S2 = 0.f;
        for (int w = 0; w < 8; w++) { S += rs[w]; S2 += rs2[w]; }
        float mu = S * (1.f / 2048.f);
        float var = S2 * (1.f / 2048.f) - mu * mu;
        s_mean = mu;
        s_rstd = rsqrtf(var + 1e-5f);
    }
    __syncthreads();
    float mu = s_mean, rstd = s_rstd;
    float* y = Y + (long)row * Dz;
#pragma unroll
    for (int r = 0; r < 8; r++) {
        int c = r * 256 + tid;
        y[c] = (v[r] - mu) * rstd * gamma[c] + beta[c];
    }
}

// ---------------------------------------------------------------------------
extern "C" void kernel_launch(void* const* d_in, const int* in_sizes, int n_in,
                              void* d_out, int out_size)
{
    const float* q_input  = (const float*)d_in[0];
    const float* kv_input = (const float*)d_in[1];
    const int*   mask     = (const int*)d_in[2];    // bool -> int32 in harness
    const float* Wq = (const float*)d_in[3];
    const float* Wk = (const float*)d_in[4];
    const float* Wv = (const float*)d_in[5];
    const float* Wo = (const float*)d_in[6];
    const float* ln_gamma = (const float*)d_in[7];
    const float* ln_beta  = (const float*)d_in[8];
    const float* rope_cos = (const float*)d_in[9];
    const float* rope_sin = (const float*)d_in[10];
    float* out = (float*)d_out;

    float *pQ, *pK, *pV, *pA, *pR;
    cudaGetSymbolAddress((void**)&pQ, g_Q);
    cudaGetSymbolAddress((void**)&pK, g_K);
    cudaGetSymbolAddress((void**)&pV, g_V);
    cudaGetSymbolAddress((void**)&pA, g_A);
    cudaGetSymbolAddress((void**)&pR, g_R);

    cudaFuncSetAttribute(flash_kernel,
                         cudaFuncAttributeMaxDynamicSharedMemorySize, FL_SMEM);

    const int M = Bz * Sz;   // 8192
    dim3 ggrid(Dz / 128, M / 128);   // (16, 64)

    gemm128<<<ggrid, 256>>>(q_input,  Wq, nullptr, pQ, M, Dz, Dz);
    gemm128<<<ggrid, 256>>>(kv_input, Wk, nullptr, pK, M, Dz, Dz);
    gemm128<<<ggrid, 256>>>(kv_input, Wv, nullptr, pV, M, Dz, Dz);

    int rope_threads = Bz * Sz * NHz * 64;   // 8388608
    rope_kernel<<<rope_threads / 256, 256>>>(pQ, rope_cos, rope_sin);
    rope_kernel<<<rope_threads / 256, 256>>>(pK, rope_cos, rope_sin);

    flash_kernel<<<Bz * NHz * (Sz / 64), 256, FL_SMEM>>>(pQ, pK, pV, mask, pA);

    gemm128<<<ggrid, 256>>>(pA, Wo, q_input, pR, M, Dz, Dz);

    ln_kernel<<<M, 256>>>(pR, ln_gamma, ln_beta, out);
}